// round 2
// baseline (speedup 1.0000x reference)
#include <cuda_runtime.h>

#define Ssz   2304
#define Csz   256
#define Bbat  8
#define BSC   (Bbat*Ssz*Csz)

// ---- scratch: __device__ globals (allowed; no cudaMalloc anywhere) ---------
__device__ float g_xln[2][BSC];
__device__ float g_q[2][BSC];
__device__ float g_k[2][BSC];
__device__ float g_v[2][BSC];
__device__ float g_E[(size_t)Bbat*Ssz*Ssz];
__device__ float g_invD[(size_t)Ssz*Ssz];
__device__ float g_O[BSC];

// ---- helpers ---------------------------------------------------------------
__device__ __forceinline__ float tf32r(float x) {
    unsigned u; asm("cvt.rna.tf32.f32 %0, %1;" : "=r"(u) : "f"(x));
    return __uint_as_float(u);
}
__device__ __forceinline__ void mma_tf32(float acc[4], const unsigned a[4], const unsigned b[2]) {
    asm volatile(
        "mma.sync.aligned.m16n8k8.row.col.f32.tf32.tf32.f32 "
        "{%0,%1,%2,%3}, {%4,%5,%6,%7}, {%8,%9}, {%0,%1,%2,%3};\n"
        : "+f"(acc[0]), "+f"(acc[1]), "+f"(acc[2]), "+f"(acc[3])
        : "r"(a[0]), "r"(a[1]), "r"(a[2]), "r"(a[3]), "r"(b[0]), "r"(b[1]));
}

// ---- LayerNorm over C + transpose [B,C,S] -> [B,S,C] -----------------------
// grid (S/32, B, 2), 256 threads
__global__ __launch_bounds__(256, 2) void ln_kernel(
    const float* __restrict__ xl, const float* __restrict__ xr,
    const float* __restrict__ g1, const float* __restrict__ b1,
    const float* __restrict__ g2, const float* __restrict__ b2,
    float* __restrict__ xlnL, float* __restrict__ xlnR)
{
    const int side = blockIdx.z;
    const float* x  = side ? xr : xl;
    const float* g  = side ? g2 : g1;
    const float* bb = side ? b2 : b1;
    float* xo = side ? xlnR : xlnL;

    const int b  = blockIdx.y;
    const int s0 = blockIdx.x * 32;
    const int tid = threadIdx.x;
    const int tx = tid & 31, ty = tid >> 5;

    __shared__ float xs[256][33];
    __shared__ float ps[8][32], ps2[8][32];
    __shared__ float mu[32], rs[32];

    const float* xb = x + (size_t)b * Csz * Ssz;
    #pragma unroll
    for (int cc = 0; cc < 32; cc++) {
        int c = cc * 8 + ty;
        xs[c][tx] = xb[(size_t)c * Ssz + s0 + tx];
    }
    __syncthreads();

    float sum = 0.f, sq = 0.f;
    #pragma unroll
    for (int i = 0; i < 32; i++) {
        float v = xs[ty * 32 + i][tx];
        sum += v; sq += v * v;
    }
    ps[ty][tx] = sum; ps2[ty][tx] = sq;
    __syncthreads();

    if (ty == 0) {
        float s1 = 0.f, s2 = 0.f;
        #pragma unroll
        for (int j = 0; j < 8; j++) { s1 += ps[j][tx]; s2 += ps2[j][tx]; }
        float m = s1 * (1.f / 256.f);
        float v = s2 * (1.f / 256.f) - m * m;
        mu[tx] = m;
        rs[tx] = rsqrtf(v + 1e-5f);
    }
    __syncthreads();

    const float gc = g[tid], bc = bb[tid];
    float* xob = xo + ((size_t)b * Ssz + s0) * Csz;
    #pragma unroll
    for (int si = 0; si < 32; si++)
        xob[si * Csz + tid] = (xs[tid][si] - mu[si]) * rs[si] * gc + bc;
}

// ---- TF32 GEMM: C[M,256] = (A .* Asc?) @ Bw, tiles 128x128x32 --------------
// MODE 0: plain store to C.  MODE 1: out = resid + acc, transposed to [B,C,S].
template<int MODE>
__global__ __launch_bounds__(256, 1) void gemm_nn(
    const float* __restrict__ A, int lda, long sA,
    const float* __restrict__ Bw, long sB,
    const float* __restrict__ Asc,
    float* __restrict__ C, long sC, int K,
    const float* __restrict__ resid)
{
    const int tid = threadIdx.x, lane = tid & 31, warp = tid >> 5;
    const int wm = (warp >> 2) * 64, wn = (warp & 3) * 32;
    const int grp = lane >> 2, tg = lane & 3;
    const int n0 = blockIdx.x * 128, m0 = blockIdx.y * 128;
    A  += (long)blockIdx.z * sA;
    Bw += (long)blockIdx.z * sB;
    C  += (long)blockIdx.z * sC;

    __shared__ float As[128 * 36];
    __shared__ float Bs[32 * 136];

    float acc[4][4][4];
    #pragma unroll
    for (int i = 0; i < 4; i++)
        #pragma unroll
        for (int j = 0; j < 4; j++)
            #pragma unroll
            for (int r = 0; r < 4; r++) acc[i][j][r] = 0.f;

    const int rA = tid >> 3, cA = (tid & 7) * 4;
    const int rB = tid >> 5, cB = (tid & 31) * 4;
    float4 pa[4], pb[4];

    auto ldAB = [&](int kc) {
        #pragma unroll
        for (int i = 0; i < 4; i++) {
            long offA = (long)(m0 + rA + i * 32) * lda + kc * 32 + cA;
            float4 va = *reinterpret_cast<const float4*>(&A[offA]);
            if (Asc) {
                float4 vs = *reinterpret_cast<const float4*>(&Asc[offA]);
                va.x *= vs.x; va.y *= vs.y; va.z *= vs.z; va.w *= vs.w;
            }
            pa[i] = va;
            pb[i] = *reinterpret_cast<const float4*>(&Bw[(long)(kc * 32 + rB + i * 8) * 256 + n0 + cB]);
        }
    };
    auto stAB = [&]() {
        #pragma unroll
        for (int i = 0; i < 4; i++) {
            int r = rA + i * 32;
            As[r * 36 + cA + 0] = tf32r(pa[i].x);
            As[r * 36 + cA + 1] = tf32r(pa[i].y);
            As[r * 36 + cA + 2] = tf32r(pa[i].z);
            As[r * 36 + cA + 3] = tf32r(pa[i].w);
            int rb = rB + i * 8;
            Bs[rb * 136 + cB + 0] = tf32r(pb[i].x);
            Bs[rb * 136 + cB + 1] = tf32r(pb[i].y);
            Bs[rb * 136 + cB + 2] = tf32r(pb[i].z);
            Bs[rb * 136 + cB + 3] = tf32r(pb[i].w);
        }
    };

    const int nk = K >> 5;
    ldAB(0); stAB(); __syncthreads();
    for (int kc = 0; kc < nk; kc++) {
        if (kc + 1 < nk) ldAB(kc + 1);
        #pragma unroll
        for (int ks = 0; ks < 4; ks++) {
            const int k0 = ks * 8;
            unsigned af[4][4], bf[4][2];
            #pragma unroll
            for (int mi = 0; mi < 4; mi++) {
                int rm = wm + mi * 16;
                af[mi][0] = __float_as_uint(As[(rm + grp    ) * 36 + k0 + tg    ]);
                af[mi][1] = __float_as_uint(As[(rm + grp + 8) * 36 + k0 + tg    ]);
                af[mi][2] = __float_as_uint(As[(rm + grp    ) * 36 + k0 + tg + 4]);
                af[mi][3] = __float_as_uint(As[(rm + grp + 8) * 36 + k0 + tg + 4]);
            }
            #pragma unroll
            for (int ni = 0; ni < 4; ni++) {
                int cn = wn + ni * 8 + grp;
                bf[ni][0] = __float_as_uint(Bs[(k0 + tg    ) * 136 + cn]);
                bf[ni][1] = __float_as_uint(Bs[(k0 + tg + 4) * 136 + cn]);
            }
            #pragma unroll
            for (int mi = 0; mi < 4; mi++)
                #pragma unroll
                for (int ni = 0; ni < 4; ni++)
                    mma_tf32(acc[mi][ni], af[mi], bf[ni]);
        }
        __syncthreads();
        if (kc + 1 < nk) { stAB(); __syncthreads(); }
    }

    #pragma unroll
    for (int mi = 0; mi < 4; mi++) {
        #pragma unroll
        for (int ni = 0; ni < 4; ni++) {
            if (MODE == 0) {
                int r0 = m0 + wm + mi * 16 + grp;
                int c0 = n0 + wn + ni * 8 + tg * 2;
                *reinterpret_cast<float2*>(&C[(long)r0 * 256 + c0]) =
                    make_float2(acc[mi][ni][0], acc[mi][ni][1]);
                *reinterpret_cast<float2*>(&C[(long)(r0 + 8) * 256 + c0]) =
                    make_float2(acc[mi][ni][2], acc[mi][ni][3]);
            } else {
                int m  = m0 + wm + mi * 16 + grp;
                int bb = m / Ssz;
                int ss = m - bb * Ssz;
                int c  = n0 + wn + ni * 8 + tg * 2;
                long o0 = ((long)bb * 256 + c) * Ssz + ss;
                C[o0          ] = resid[o0          ] + acc[mi][ni][0];
                C[o0 + Ssz    ] = resid[o0 + Ssz    ] + acc[mi][ni][1];
                C[o0 + 8      ] = resid[o0 + 8      ] + acc[mi][ni][2];
                C[o0 + Ssz + 8] = resid[o0 + Ssz + 8] + acc[mi][ni][3];
            }
        }
    }
}

// ---- scores: E[b,s,t] = exp(Q[b,s,:].K[b,t,:]/16), all 8 batches per CTA ---
// grid (S/128 t, S/128 s), 256 threads
__global__ __launch_bounds__(256, 1) void attn_scores(
    const float* __restrict__ Q, const float* __restrict__ Ko,
    float* __restrict__ E)
{
    const int tid = threadIdx.x, lane = tid & 31, warp = tid >> 5;
    const int wm = (warp >> 2) * 64, wn = (warp & 3) * 32;
    const int grp = lane >> 2, tg = lane & 3;
    const int t0 = blockIdx.x * 128, s0 = blockIdx.y * 128;

    __shared__ float As[128 * 36];   // Q tile [s][k]
    __shared__ float Bs[128 * 36];   // K tile [t][k]

    const int rA = tid >> 3, cA = (tid & 7) * 4;
    float4 pa[4], pb[4];

    auto ld = [&](int it) {
        int b = it >> 3, kc = it & 7;
        #pragma unroll
        for (int i = 0; i < 4; i++) {
            pa[i] = *reinterpret_cast<const float4*>(
                &Q [((long)b * Ssz + s0 + rA + i * 32) * 256 + kc * 32 + cA]);
            pb[i] = *reinterpret_cast<const float4*>(
                &Ko[((long)b * Ssz + t0 + rA + i * 32) * 256 + kc * 32 + cA]);
        }
    };
    auto st = [&]() {
        #pragma unroll
        for (int i = 0; i < 4; i++) {
            int r = rA + i * 32;
            As[r * 36 + cA + 0] = tf32r(pa[i].x);
            As[r * 36 + cA + 1] = tf32r(pa[i].y);
            As[r * 36 + cA + 2] = tf32r(pa[i].z);
            As[r * 36 + cA + 3] = tf32r(pa[i].w);
            Bs[r * 36 + cA + 0] = tf32r(pb[i].x);
            Bs[r * 36 + cA + 1] = tf32r(pb[i].y);
            Bs[r * 36 + cA + 2] = tf32r(pb[i].z);
            Bs[r * 36 + cA + 3] = tf32r(pb[i].w);
        }
    };

    float acc[4][4][4];
    ld(0); st(); __syncthreads();
    for (int it = 0; it < 64; it++) {
        const int kc = it & 7;
        if (kc == 0) {
            #pragma unroll
            for (int i = 0; i < 4; i++)
                #pragma unroll
                for (int j = 0; j < 4; j++)
                    #pragma unroll
                    for (int r = 0; r < 4; r++) acc[i][j][r] = 0.f;
        }
        if (it + 1 < 64) ld(it + 1);
        #pragma unroll
        for (int ks = 0; ks < 4; ks++) {
            const int k0 = ks * 8;
            unsigned af[4][4], bf[4][2];
            #pragma unroll
            for (int mi = 0; mi < 4; mi++) {
                int rm = wm + mi * 16;
                af[mi][0] = __float_as_uint(As[(rm + grp    ) * 36 + k0 + tg    ]);
                af[mi][1] = __float_as_uint(As[(rm + grp + 8) * 36 + k0 + tg    ]);
                af[mi][2] = __float_as_uint(As[(rm + grp    ) * 36 + k0 + tg + 4]);
                af[mi][3] = __float_as_uint(As[(rm + grp + 8) * 36 + k0 + tg + 4]);
            }
            #pragma unroll
            for (int ni = 0; ni < 4; ni++) {
                int cn = wn + ni * 8 + grp;
                bf[ni][0] = __float_as_uint(Bs[cn * 36 + k0 + tg    ]);
                bf[ni][1] = __float_as_uint(Bs[cn * 36 + k0 + tg + 4]);
            }
            #pragma unroll
            for (int mi = 0; mi < 4; mi++)
                #pragma unroll
                for (int ni = 0; ni < 4; ni++)
                    mma_tf32(acc[mi][ni], af[mi], bf[ni]);
        }
        __syncthreads();
        if (it + 1 < 64) st();
        if (kc == 7) {
            const int b = it >> 3;
            float* Eb = E + (long)b * Ssz * Ssz;
            #pragma unroll
            for (int mi = 0; mi < 4; mi++) {
                #pragma unroll
                for (int ni = 0; ni < 4; ni++) {
                    int r0 = s0 + wm + mi * 16 + grp;
                    int c0 = t0 + wn + ni * 8 + tg * 2;
                    float e0 = __expf(acc[mi][ni][0] * 0.0625f);
                    float e1 = __expf(acc[mi][ni][1] * 0.0625f);
                    float e2 = __expf(acc[mi][ni][2] * 0.0625f);
                    float e3 = __expf(acc[mi][ni][3] * 0.0625f);
                    *reinterpret_cast<float2*>(&Eb[(long)r0 * Ssz + c0]) = make_float2(e0, e1);
                    *reinterpret_cast<float2*>(&Eb[(long)(r0 + 8) * Ssz + c0]) = make_float2(e2, e3);
                }
            }
        }
        if (it + 1 < 64) __syncthreads();
    }
}

// ---- invD[s,t] = 1 / sum_b E[b,s,t] ----------------------------------------
__global__ __launch_bounds__(256, 4) void denom_kernel(
    const float* __restrict__ E, float* __restrict__ invD)
{
    const long SS = (long)Ssz * Ssz;
    long i = ((long)blockIdx.x * 256 + threadIdx.x) * 4;
    float4 s = make_float4(0.f, 0.f, 0.f, 0.f);
    #pragma unroll
    for (int b = 0; b < Bbat; b++) {
        float4 e = *reinterpret_cast<const float4*>(&E[b * SS + i]);
        s.x += e.x; s.y += e.y; s.z += e.z; s.w += e.w;
    }
    *reinterpret_cast<float4*>(&invD[i]) =
        make_float4(1.f / s.x, 1.f / s.y, 1.f / s.z, 1.f / s.w);
}

// ---- launch ----------------------------------------------------------------
extern "C" void kernel_launch(void* const* d_in, const int* in_sizes, int n_in,
                              void* d_out, int out_size) {
    const float* x_l = (const float*)d_in[0];
    const float* x_r = (const float*)d_in[1];
    const float* Wq  = (const float*)d_in[2];
    const float* Wk  = (const float*)d_in[3];
    const float* Wv  = (const float*)d_in[4];
    const float* Wo  = (const float*)d_in[5];
    const float* g1  = (const float*)d_in[6];
    const float* b1  = (const float*)d_in[7];
    const float* g2  = (const float*)d_in[8];
    const float* b2  = (const float*)d_in[9];
    float* out = (float*)d_out;

    float *xln, *q, *k, *v, *E, *invD, *O;
    cudaGetSymbolAddress((void**)&xln,  g_xln);
    cudaGetSymbolAddress((void**)&q,    g_q);
    cudaGetSymbolAddress((void**)&k,    g_k);
    cudaGetSymbolAddress((void**)&v,    g_v);
    cudaGetSymbolAddress((void**)&E,    g_E);
    cudaGetSymbolAddress((void**)&invD, g_invD);
    cudaGetSymbolAddress((void**)&O,    g_O);

    ln_kernel<<<dim3(Ssz / 32, Bbat, 2), 256>>>(x_l, x_r, g1, b1, g2, b2,
                                                xln, xln + BSC);

    const dim3 gProj(2, (Bbat * Ssz) / 128, 1);
    for (int s = 0; s < 2; s++) {
        gemm_nn<0><<<gProj, 256>>>(xln + s * BSC, 256, 0, Wq, 0, nullptr,
                                   q + s * BSC, 0, 256, nullptr);
        gemm_nn<0><<<gProj, 256>>>(xln + s * BSC, 256, 0, Wk, 0, nullptr,
                                   k + s * BSC, 0, 256, nullptr);
        gemm_nn<0><<<gProj, 256>>>(xln + s * BSC, 256, 0, Wv, 0, nullptr,
                                   v + s * BSC, 0, 256, nullptr);
    }

    const long SS = (long)Ssz * Ssz;
    for (int s = 0; s < 2; s++) {
        attn_scores<<<dim3(Ssz / 128, Ssz / 128), 256>>>(q + s * BSC,
                                                         k + (1 - s) * BSC, E);
        denom_kernel<<<(int)(SS / 1024), 256>>>(E, invD);
        gemm_nn<0><<<dim3(2, Ssz / 128, Bbat), 256>>>(E, Ssz, SS,
                                                      v + s * BSC, (long)Ssz * 256, invD,
                                                      O, (long)Ssz * 256, Ssz, nullptr);
        gemm_nn<1><<<gProj, 256>>>(O, 256, 0, Wo, 0, nullptr,
                                   out + s * BSC, 0, 256, s ? x_r : x_l);
    }
}